// round 4
// baseline (speedup 1.0000x reference)
#include <cuda_runtime.h>
#include <math.h>

#define BB 4
#define CC 64
#define NN 4096
#define RR 4
#define EPSF 1e-6f
#define PSS 68   // padded row stride for P tile (floats)

typedef unsigned long long u64;

// -------- packed f32x2 helpers (Blackwell FFMA2 path, PTX-only) --------
__device__ __forceinline__ u64 pk2(float lo, float hi) {
    u64 r; asm("mov.b64 %0, {%1,%2};" : "=l"(r) : "f"(lo), "f"(hi)); return r;
}
__device__ __forceinline__ void upk2(u64 v, float& lo, float& hi) {
    asm("mov.b64 {%0,%1}, %2;" : "=f"(lo), "=f"(hi) : "l"(v));
}
__device__ __forceinline__ u64 ffma2(u64 a, u64 b, u64 c) {
    u64 d; asm("fma.rn.f32x2 %0, %1, %2, %3;" : "=l"(d) : "l"(a), "l"(b), "l"(c)); return d;
}
__device__ __forceinline__ u64 fmul2(u64 a, u64 b) {
    u64 d; asm("mul.rn.f32x2 %0, %1, %2;" : "=l"(d) : "l"(a), "l"(b)); return d;
}

// -------- FMA-pipe exp (avoids MUFU; rel err ~2e-6) --------
// exp(x) = 2^(x*log2e). Round via magic-number; n<<23 recovered directly from
// the magic float's bits (0x400000<<23 wraps to 0 in int32).
__device__ __forceinline__ float fexp(float x) {
    const float LOG2E = 1.4426950408889634f;
    const float MAGIC = 12582912.0f;            // 1.5 * 2^23
    x = fmaxf(x, -80.0f);
    float nf = fmaf(x, LOG2E, MAGIC);
    float nv = nf - MAGIC;
    float f  = fmaf(x, LOG2E, -nv);             // f in [-0.5, 0.5]
    // 2^f Taylor deg-5 (Horner), coeffs (ln2)^k/k!
    float p = 1.3333558146e-3f;
    p = fmaf(p, f, 9.6181298421e-3f);
    p = fmaf(p, f, 5.5504108665e-2f);
    p = fmaf(p, f, 2.4022650696e-1f);
    p = fmaf(p, f, 6.9314718056e-1f);
    p = fmaf(p, f, 1.0f);
    int r = __float_as_int(p) + (__float_as_int(nf) << 23);
    return __int_as_float(r);
}

// -------- scratch (device globals; no allocation allowed) --------
__device__ float g_stat[BB][CC][6];        // s1,q1,s2,q2,sx,qx per (b,c)
__device__ float g_se[BB][CC];             // SE sigmoid gate
__device__ float g_W[5][BB][CC][CC];       // folded weights, [ci][co]
__device__ float g_bias[5][BB][CC];        // folded bias
__device__ float g_proj[5][BB][CC][NN];    // q1,k1,q2,k2,v  [c][n]
__device__ float g_h[2][BB][CC][NN];       // attention outputs per branch

// ================= kernel 1: per-(b,c) sums over HW =================
__global__ void k_stats(const float* __restrict__ x1, const float* __restrict__ x2) {
    int bc = blockIdx.x;                       // b*CC + c
    const float* p1 = x1 + (size_t)bc * NN;
    const float* p2 = x2 + (size_t)bc * NN;
    float s1=0.f,q1=0.f,s2=0.f,q2=0.f,sx=0.f,qx=0.f;
    for (int i = threadIdx.x; i < NN; i += 256) {
        float a = p1[i], b_ = p2[i], s = a + b_;
        s1 += a; q1 += a*a; s2 += b_; q2 += b_*b_; sx += s; qx += s*s;
    }
    __shared__ float red[6][256];
    red[0][threadIdx.x]=s1; red[1][threadIdx.x]=q1; red[2][threadIdx.x]=s2;
    red[3][threadIdx.x]=q2; red[4][threadIdx.x]=sx; red[5][threadIdx.x]=qx;
    __syncthreads();
    for (int off=128; off>=1; off>>=1) {
        if (threadIdx.x < (unsigned)off) {
            #pragma unroll
            for (int k=0;k<6;k++) red[k][threadIdx.x] += red[k][threadIdx.x+off];
        }
        __syncthreads();
    }
    if (threadIdx.x < 6) g_stat[bc/CC][bc%CC][threadIdx.x] = red[threadIdx.x][0];
}

// ============ kernel 2: SE MLP + GroupNorm fold into weights ============
__global__ void k_prep(const float* __restrict__ se_w1, const float* __restrict__ se_w2,
                       const float* __restrict__ gamma, const float* __restrict__ beta,
                       const float* __restrict__ wq, const float* __restrict__ bq,
                       const float* __restrict__ wk, const float* __restrict__ bk,
                       const float* __restrict__ wv, const float* __restrict__ bv) {
    int b = blockIdx.x;
    int c = threadIdx.x;   // 0..63
    __shared__ float sy[CC], sh[RR], sA[3][CC], sBc[3][CC];
    float st[6], stp[6];
    #pragma unroll
    for (int k=0;k<6;k++) st[k] = g_stat[b][c][k];
    int cp = c ^ 1;  // group partner channel (groups of 2)
    #pragma unroll
    for (int k=0;k<6;k++) stp[k] = g_stat[b][cp][k];

    sy[c] = st[4] * (1.0f/NN);                 // SE mean of x = x1+x2
    __syncthreads();
    if (c < RR) {
        float h = 0.f;
        for (int ci=0; ci<CC; ci++) h += se_w1[c*CC+ci]*sy[ci];
        sh[c] = fmaxf(h, 0.f);
    }
    __syncthreads();
    {
        float z = 0.f;
        #pragma unroll
        for (int r=0;r<RR;r++) z += se_w2[c*RR+r]*sh[r];
        g_se[b][c] = 1.f/(1.f+fexp(-z));
    }
    const float inv = 1.0f/(2.0f*NN);
    float ga = gamma[c], be = beta[c];
    #pragma unroll
    for (int t=0;t<3;t++) {                     // t=0:x1, 1:x2, 2:x
        float mean = (st[2*t]+stp[2*t])*inv;
        float var  = (st[2*t+1]+stp[2*t+1])*inv - mean*mean;
        float rs = rsqrtf(var + EPSF);
        float A = rs*ga;
        sA[t][c] = A;
        sBc[t][c] = be - mean*A;
    }
    __syncthreads();
    // fold GN affine into each projection's weights (per batch)
    for (int p=0;p<5;p++) {
        const float* w  = (p==0||p==2)? wq : (p==1||p==3)? wk : wv;
        const float* bb = (p==0||p==2)? bq : (p==1||p==3)? bk : bv;
        int t = (p<2)?0 : (p<4)?1 : 2;
        float acc = bb[c];
        for (int ci=0; ci<CC; ci++) {
            float wvl = w[c*CC+ci];
            acc += wvl * sBc[t][ci];
            g_W[p][b][ci][c] = wvl * sA[t][ci];   // transposed for proj kernel
        }
        g_bias[p][b][c] = acc;
    }
}

// ================= kernel 3: the five 1x1-conv projections =================
__global__ void __launch_bounds__(256) k_proj(const float* __restrict__ x1,
                                              const float* __restrict__ x2) {
    int nt = blockIdx.x, p = blockIdx.y, b = blockIdx.z;
    int n0 = nt * 64;
    __shared__ float xs[CC][64];
    __shared__ float Wt[CC][CC];
    __shared__ float bias[CC];
    int tid = threadIdx.x;
    const float* s1 = x1 + (size_t)b*CC*NN + n0;
    const float* s2 = x2 + (size_t)b*CC*NN + n0;
    for (int idx = tid; idx < CC*64; idx += 256) {
        int ci = idx >> 6, n = idx & 63;
        float v;
        if (p < 2)       v = s1[(size_t)ci*NN + n];
        else if (p < 4)  v = s2[(size_t)ci*NN + n];
        else             v = s1[(size_t)ci*NN + n] + s2[(size_t)ci*NN + n];
        xs[ci][n] = v;
    }
    for (int idx = tid; idx < CC*CC; idx += 256)
        (&Wt[0][0])[idx] = (&g_W[p][b][0][0])[idx];
    if (tid < CC) bias[tid] = g_bias[p][b][tid];
    __syncthreads();

    int cg = tid >> 4;     // co block: 4*cg..
    int ng = tid & 15;     // n  block: 4*ng..
    float acc[4][4];
    #pragma unroll
    for (int i=0;i<4;i++){ float bv_ = bias[4*cg+i];
        #pragma unroll
        for (int j=0;j<4;j++) acc[i][j]=bv_; }
    for (int ci=0; ci<CC; ci++) {
        float4 w4 = *(const float4*)&Wt[ci][4*cg];
        float4 x4 = *(const float4*)&xs[ci][4*ng];
        float wa[4]={w4.x,w4.y,w4.z,w4.w};
        float xa[4]={x4.x,x4.y,x4.z,x4.w};
        #pragma unroll
        for (int i=0;i<4;i++)
            #pragma unroll
            for (int j=0;j<4;j++) acc[i][j] += wa[i]*xa[j];
    }
    float* out = &g_proj[p][b][0][0] + n0;
    #pragma unroll
    for (int i=0;i<4;i++) {
        float4 v = make_float4(acc[i][0],acc[i][1],acc[i][2],acc[i][3]);
        *(float4*)&out[(size_t)(4*cg+i)*NN + 4*ng] = v;
    }
}

// ============== kernel 4: flash attention (64q tile, f32x2 math) ==============
// 128 threads. Per kt-iter (64 keys):
//   S:  thread tile 4i x 8j (j-quads {jq, jq+8}), packed FFMA2
//   PV: thread tile 4i x 8c, packed FFMA2 over j-pairs; acc lanes = even/odd j
// K/V tiles quad-XOR swizzled for conflict-free LDS. exp on FMA pipe (fexp).
__global__ void __launch_bounds__(128, 3) k_attn() {
    extern __shared__ float sm[];
    float* Qs = sm;                 // [c][i]  4096 (pre-scaled by 0.125)
    float* Ks = Qs + 4096;          // [c][j]  quad-swizzled
    float* Vs = Ks + 4096;          // [c][j]  quad-swizzled
    float* Ps = Vs + 4096;          // [i][j]  stride PSS
    __shared__ float rm[64], rl[64], rcorr[64];

    int qt = blockIdx.x;
    int bbi = blockIdx.y;
    int b = bbi >> 1, br = bbi & 1;
    const float* Q  = &g_proj[br?2:0][b][0][0] + qt*64;
    const float* Kp = &g_proj[br?3:1][b][0][0];
    const float* Vp = &g_proj[4][b][0][0];
    int tid = threadIdx.x;

    if (tid < 64) { rm[tid] = -INFINITY; rl[tid] = 0.f; }

    // load Q tile (scaled): 1024 float4s over 128 threads
    for (int idx4 = tid; idx4 < 1024; idx4 += 128) {
        int c = idx4 >> 4, i4 = (idx4 & 15) << 2;
        float4 v = *(const float4*)&Q[(size_t)c*NN + i4];
        v.x *= 0.125f; v.y *= 0.125f; v.z *= 0.125f; v.w *= 0.125f;
        *(float4*)&Qs[c*64 + i4] = v;
    }

    int iq = tid >> 3;          // i block (0..15): i = 4*iq+di
    int jq = tid & 7;           // j quads {jq, jq+8}
    int cq = tid & 7;           // PV: c = cq + 8*m
    int rr = tid >> 1, seg = tid & 1;  // softmax: 2 threads/row

    u64 acc[4][8];              // O accumulators, f32x2 (even/odd j lanes)
    #pragma unroll
    for (int i=0;i<4;i++)
        #pragma unroll
        for (int m=0;m<8;m++) acc[i][m] = 0ull;

    for (int kt = 0; kt < 64; kt++) {
        __syncthreads();                 // Ks/Vs/Ps safe to overwrite
        int j0 = kt*64;
        // ---- load K,V tile, swizzled: quad q4 -> q4 ^ (c&15) ----
        for (int idx4 = tid; idx4 < 1024; idx4 += 128) {
            int c = idx4 >> 4, q4 = idx4 & 15;
            int j = q4 << 2;
            float4 kv = *(const float4*)&Kp[(size_t)c*NN + j0 + j];
            float4 vv = *(const float4*)&Vp[(size_t)c*NN + j0 + j];
            int sq = ((q4 ^ (c & 15)) << 2);
            *(float4*)&Ks[c*64 + sq] = kv;
            *(float4*)&Vs[c*64 + sq] = vv;
        }
        __syncthreads();
        // ---- S = (Q*0.125)^T K : s2[di][0..1] = quad jq, [2..3] = quad jq+8 ----
        {
            u64 s2[4][4];
            #pragma unroll
            for (int i=0;i<4;i++)
                #pragma unroll
                for (int u=0;u<4;u++) s2[i][u] = 0ull;
            #pragma unroll 4
            for (int c_=0; c_<64; c_++) {
                float4 qv = *(const float4*)&Qs[c_*64 + 4*iq];
                u64 qd0 = pk2(qv.x, qv.x);
                u64 qd1 = pk2(qv.y, qv.y);
                u64 qd2 = pk2(qv.z, qv.z);
                u64 qd3 = pk2(qv.w, qv.w);
                int s = c_ & 15;
                ulonglong2 ka = *(const ulonglong2*)&Ks[c_*64 + 4*(jq ^ s)];
                ulonglong2 kb = *(const ulonglong2*)&Ks[c_*64 + 4*((jq + 8) ^ s)];
                s2[0][0]=ffma2(qd0,ka.x,s2[0][0]); s2[0][1]=ffma2(qd0,ka.y,s2[0][1]);
                s2[0][2]=ffma2(qd0,kb.x,s2[0][2]); s2[0][3]=ffma2(qd0,kb.y,s2[0][3]);
                s2[1][0]=ffma2(qd1,ka.x,s2[1][0]); s2[1][1]=ffma2(qd1,ka.y,s2[1][1]);
                s2[1][2]=ffma2(qd1,kb.x,s2[1][2]); s2[1][3]=ffma2(qd1,kb.y,s2[1][3]);
                s2[2][0]=ffma2(qd2,ka.x,s2[2][0]); s2[2][1]=ffma2(qd2,ka.y,s2[2][1]);
                s2[2][2]=ffma2(qd2,kb.x,s2[2][2]); s2[2][3]=ffma2(qd2,kb.y,s2[2][3]);
                s2[3][0]=ffma2(qd3,ka.x,s2[3][0]); s2[3][1]=ffma2(qd3,ka.y,s2[3][1]);
                s2[3][2]=ffma2(qd3,kb.x,s2[3][2]); s2[3][3]=ffma2(qd3,kb.y,s2[3][3]);
            }
            #pragma unroll
            for (int di=0; di<4; di++) {
                ulonglong2 pa; pa.x = s2[di][0]; pa.y = s2[di][1];
                ulonglong2 pb; pb.x = s2[di][2]; pb.y = s2[di][3];
                *(ulonglong2*)&Ps[(4*iq+di)*PSS + 4*jq]      = pa;
                *(ulonglong2*)&Ps[(4*iq+di)*PSS + 4*jq + 32] = pb;
            }
        }
        __syncthreads();
        // ---- online softmax: 2 threads per row, 32 cols each (FMA-pipe exp) ----
        {
            float vloc[32];
            float* prow = &Ps[rr*PSS + 32*seg];
            #pragma unroll
            for (int u=0;u<8;u++) {
                float4 v = *(const float4*)&prow[4*u];
                vloc[4*u]=v.x; vloc[4*u+1]=v.y; vloc[4*u+2]=v.z; vloc[4*u+3]=v.w;
            }
            float mx = vloc[0];
            #pragma unroll
            for (int u=1;u<32;u++) mx = fmaxf(mx, vloc[u]);
            mx = fmaxf(mx, __shfl_xor_sync(0xffffffffu, mx, 1));
            float m_old = rm[rr];
            float m_new = fmaxf(m_old, mx);
            float ls = 0.f;
            #pragma unroll
            for (int u=0;u<32;u++) { float p_ = fexp(vloc[u]-m_new); vloc[u]=p_; ls += p_; }
            ls += __shfl_xor_sync(0xffffffffu, ls, 1);
            #pragma unroll
            for (int u=0;u<8;u++)
                *(float4*)&prow[4*u] = make_float4(vloc[4*u],vloc[4*u+1],vloc[4*u+2],vloc[4*u+3]);
            if (seg == 0) {
                float corr = fexp(m_old - m_new);
                rm[rr] = m_new;
                rl[rr] = rl[rr]*corr + ls;
                rcorr[rr] = corr;
            }
        }
        __syncthreads();
        // ---- O = O*corr + P @ V^T (packed over j-pairs) ----
        {
            #pragma unroll
            for (int di=0; di<4; di++) {
                u64 crd = pk2(rcorr[4*iq+di], rcorr[4*iq+di]);
                #pragma unroll
                for (int m=0;m<8;m++) acc[di][m] = fmul2(acc[di][m], crd);
            }
            #pragma unroll 2
            for (int j4=0; j4<16; j4++) {
                ulonglong2 p2[4];
                #pragma unroll
                for (int di=0; di<4; di++)
                    p2[di] = *(const ulonglong2*)&Ps[(4*iq+di)*PSS + 4*j4];
                #pragma unroll
                for (int m=0;m<8;m++) {
                    int c_ = cq + 8*m;
                    ulonglong2 v2 = *(const ulonglong2*)&Vs[c_*64 + 4*(j4 ^ (c_ & 15))];
                    acc[0][m] = ffma2(p2[0].x, v2.x, acc[0][m]);
                    acc[0][m] = ffma2(p2[0].y, v2.y, acc[0][m]);
                    acc[1][m] = ffma2(p2[1].x, v2.x, acc[1][m]);
                    acc[1][m] = ffma2(p2[1].y, v2.y, acc[1][m]);
                    acc[2][m] = ffma2(p2[2].x, v2.x, acc[2][m]);
                    acc[2][m] = ffma2(p2[2].y, v2.y, acc[2][m]);
                    acc[3][m] = ffma2(p2[3].x, v2.x, acc[3][m]);
                    acc[3][m] = ffma2(p2[3].y, v2.y, acc[3][m]);
                }
            }
        }
    }
    // ---- finalize: horizontal add lanes, divide by row sums, write h ----
    float* H = &g_h[br][b][0][0] + qt*64;
    #pragma unroll
    for (int di=0; di<4; di++) {
        float invl = 1.0f / rl[4*iq+di];
        #pragma unroll
        for (int m=0;m<8;m++) {
            int c_ = cq + 8*m;
            float lo, hi; upk2(acc[di][m], lo, hi);
            H[(size_t)c_*NN + 4*iq + di] = (lo + hi) * invl;
        }
    }
}

// ================= kernel 5: final combine =================
__global__ void k_final(const float* __restrict__ x1, const float* __restrict__ x2,
                        float* __restrict__ out) {
    int idx4 = blockIdx.x*256 + threadIdx.x;    // over BB*CC*NN/4
    if (idx4 >= BB*CC*NN/4) return;
    int idx = idx4 * 4;
    int bc = idx >> 12;
    int b = bc >> 6, c = bc & 63;
    float se = g_se[b][c];
    float4 a1 = *(const float4*)&x1[idx];
    float4 a2 = *(const float4*)&x2[idx];
    float4 h1 = *(const float4*)(&g_h[0][0][0][0] + idx);
    float4 h2 = *(const float4*)(&g_h[1][0][0][0] + idx);
    float xs[4] = {a1.x+a2.x, a1.y+a2.y, a1.z+a2.z, a1.w+a2.w};
    float h1a[4]={h1.x,h1.y,h1.z,h1.w};
    float h2a[4]={h2.x,h2.y,h2.z,h2.w};
    float oa[4];
    #pragma unroll
    for (int k=0;k<4;k++) {
        float w = 1.f/(1.f+fexp(-xs[k]*se));
        oa[k] = 2.f*h1a[k]*w + 2.f*h2a[k]*(1.f-w);
    }
    *(float4*)&out[idx] = make_float4(oa[0],oa[1],oa[2],oa[3]);
}

// ================= launcher =================
extern "C" void kernel_launch(void* const* d_in, const int* in_sizes, int n_in,
                              void* d_out, int out_size) {
    const float* x1    = (const float*)d_in[0];
    const float* x2    = (const float*)d_in[1];
    const float* se_w1 = (const float*)d_in[2];
    const float* se_w2 = (const float*)d_in[3];
    const float* gam   = (const float*)d_in[4];
    const float* bet   = (const float*)d_in[5];
    const float* wq    = (const float*)d_in[6];
    const float* bq    = (const float*)d_in[7];
    const float* wk    = (const float*)d_in[8];
    const float* bk    = (const float*)d_in[9];
    const float* wv    = (const float*)d_in[10];
    const float* bv    = (const float*)d_in[11];
    float* out = (float*)d_out;

    k_stats<<<BB*CC, 256>>>(x1, x2);
    k_prep<<<BB, CC>>>(se_w1, se_w2, gam, bet, wq, bq, wk, bk, wv, bv);
    k_proj<<<dim3(64, 5, BB), 256>>>(x1, x2);
    cudaFuncSetAttribute(k_attn, cudaFuncAttributeMaxDynamicSharedMemorySize, 66560);
    k_attn<<<dim3(64, 8), 128, 66560>>>();
    k_final<<<(BB*CC*NN/4 + 255)/256, 256>>>(x1, x2, out);
}

// round 6
// speedup vs baseline: 2.8874x; 2.8874x over previous
#include <cuda_runtime.h>
#include <cuda_bf16.h>
#include <math.h>
#include <stdint.h>

#define BB 4
#define CC 64
#define NN 4096
#define RR 4
#define EPSF 1e-6f
#define FSCALE 0.18033688011112042f   // 0.125 * log2(e), folded into Q

// ---------------- helpers ----------------
__device__ __forceinline__ uint32_t smem_u32(const void* p) {
    uint32_t a;
    asm("{ .reg .u64 t; cvta.to.shared.u64 t, %1; cvt.u32.u64 %0, t; }" : "=r"(a) : "l"(p));
    return a;
}
#define SWZ(off) ((off) ^ (((off) >> 3) & 0x70))   // SW128-style row swizzle

__device__ __forceinline__ void ldmx4(uint32_t* r, uint32_t addr) {
    asm volatile("ldmatrix.sync.aligned.m8n8.x4.shared.b16 {%0,%1,%2,%3}, [%4];"
        : "=r"(r[0]), "=r"(r[1]), "=r"(r[2]), "=r"(r[3]) : "r"(addr));
}
__device__ __forceinline__ void mma16816(float* d, const uint32_t* a,
                                         uint32_t b0, uint32_t b1) {
    asm volatile("mma.sync.aligned.m16n8k16.row.col.f32.bf16.bf16.f32 "
        "{%0,%1,%2,%3}, {%4,%5,%6,%7}, {%8,%9}, {%0,%1,%2,%3};"
        : "+f"(d[0]), "+f"(d[1]), "+f"(d[2]), "+f"(d[3])
        : "r"(a[0]), "r"(a[1]), "r"(a[2]), "r"(a[3]), "r"(b0), "r"(b1));
}
__device__ __forceinline__ uint32_t packbf(float lo, float hi) {  // {hi:upper, lo:lower}
    uint32_t r; asm("cvt.rn.bf16x2.f32 %0, %1, %2;" : "=r"(r) : "f"(hi), "f"(lo)); return r;
}
__device__ __forceinline__ float lo2f(uint32_t p) { return __int_as_float(p << 16); }
__device__ __forceinline__ float hi2f(uint32_t p) { return __int_as_float(p & 0xffff0000u); }

// FMA-pipe exp2 (keeps exps OFF the MUFU pipe; rel err ~2e-6)
__device__ __forceinline__ float fexp2(float x) {
    const float MAGIC = 12582912.0f;          // 1.5 * 2^23
    x = fmaxf(x, -80.0f);
    float nf = x + MAGIC;
    float f  = x - (nf - MAGIC);              // f in [-0.5, 0.5]
    float p = 1.3333558146e-3f;
    p = fmaf(p, f, 9.6181298421e-3f);
    p = fmaf(p, f, 5.5504108665e-2f);
    p = fmaf(p, f, 2.4022650696e-1f);
    p = fmaf(p, f, 6.9314718056e-1f);
    p = fmaf(p, f, 1.0f);
    int r = __float_as_int(p) + (__float_as_int(nf) << 23);
    return __int_as_float(r);
}
__device__ __forceinline__ float fexp(float x) {   // e^x for sigmoids
    return fexp2(x * 1.4426950408889634f);
}

// ---------------- scratch (device globals) ----------------
__device__ float g_stat[BB][CC][6];
__device__ float g_se[BB][CC];
__device__ float g_W[5][BB][CC][CC];
__device__ float g_bias[5][BB][CC];
__device__ __nv_bfloat16 g_ah[4][BB][NN][CC];   // q1,k1,q2,k2 hi   [n][c]
__device__ __nv_bfloat16 g_al[4][BB][NN][CC];   // lo
__device__ __nv_bfloat16 g_vh[BB][CC][NN];      // v hi  [c][n]
__device__ __nv_bfloat16 g_vl[BB][CC][NN];      // v lo
__device__ float g_h[2][BB][CC][NN];            // attention outputs

// ================= kernel 1: per-(b,c) sums over HW =================
__global__ void k_stats(const float* __restrict__ x1, const float* __restrict__ x2) {
    int bc = blockIdx.x;
    const float* p1 = x1 + (size_t)bc * NN;
    const float* p2 = x2 + (size_t)bc * NN;
    float s1=0.f,q1=0.f,s2=0.f,q2=0.f,sx=0.f,qx=0.f;
    for (int i = threadIdx.x; i < NN; i += 256) {
        float a = p1[i], b_ = p2[i], s = a + b_;
        s1 += a; q1 += a*a; s2 += b_; q2 += b_*b_; sx += s; qx += s*s;
    }
    __shared__ float red[6][256];
    red[0][threadIdx.x]=s1; red[1][threadIdx.x]=q1; red[2][threadIdx.x]=s2;
    red[3][threadIdx.x]=q2; red[4][threadIdx.x]=sx; red[5][threadIdx.x]=qx;
    __syncthreads();
    for (int off=128; off>=1; off>>=1) {
        if (threadIdx.x < (unsigned)off) {
            #pragma unroll
            for (int k=0;k<6;k++) red[k][threadIdx.x] += red[k][threadIdx.x+off];
        }
        __syncthreads();
    }
    if (threadIdx.x < 6) g_stat[bc/CC][bc%CC][threadIdx.x] = red[threadIdx.x][0];
}

// ============ kernel 2: SE MLP + GroupNorm fold into weights ============
__global__ void k_prep(const float* __restrict__ se_w1, const float* __restrict__ se_w2,
                       const float* __restrict__ gamma, const float* __restrict__ beta,
                       const float* __restrict__ wq, const float* __restrict__ bq,
                       const float* __restrict__ wk, const float* __restrict__ bk,
                       const float* __restrict__ wv, const float* __restrict__ bv) {
    int b = blockIdx.x;
    int c = threadIdx.x;
    __shared__ float sy[CC], sh[RR], sA[3][CC], sBc[3][CC];
    float st[6], stp[6];
    #pragma unroll
    for (int k=0;k<6;k++) st[k] = g_stat[b][c][k];
    int cp = c ^ 1;
    #pragma unroll
    for (int k=0;k<6;k++) stp[k] = g_stat[b][cp][k];

    sy[c] = st[4] * (1.0f/NN);
    __syncthreads();
    if (c < RR) {
        float h = 0.f;
        for (int ci=0; ci<CC; ci++) h += se_w1[c*CC+ci]*sy[ci];
        sh[c] = fmaxf(h, 0.f);
    }
    __syncthreads();
    {
        float z = 0.f;
        #pragma unroll
        for (int r=0;r<RR;r++) z += se_w2[c*RR+r]*sh[r];
        g_se[b][c] = 1.f/(1.f+fexp(-z));
    }
    const float inv = 1.0f/(2.0f*NN);
    float ga = gamma[c], be = beta[c];
    #pragma unroll
    for (int t=0;t<3;t++) {
        float mean = (st[2*t]+stp[2*t])*inv;
        float var  = (st[2*t+1]+stp[2*t+1])*inv - mean*mean;
        float rs = rsqrtf(var + EPSF);
        float A = rs*ga;
        sA[t][c] = A;
        sBc[t][c] = be - mean*A;
    }
    __syncthreads();
    for (int p=0;p<5;p++) {
        const float* w  = (p==0||p==2)? wq : (p==1||p==3)? wk : wv;
        const float* bb = (p==0||p==2)? bq : (p==1||p==3)? bk : bv;
        int t = (p<2)?0 : (p<4)?1 : 2;
        float acc = bb[c];
        for (int ci=0; ci<CC; ci++) {
            float wvl = w[c*CC+ci];
            acc += wvl * sBc[t][ci];
            g_W[p][b][ci][c] = wvl * sA[t][ci];
        }
        g_bias[p][b][c] = acc;
    }
}

// ====== kernel 3: projections -> bf16 hi/lo operand tensors ======
__global__ void __launch_bounds__(256) k_proj(const float* __restrict__ x1,
                                              const float* __restrict__ x2) {
    int nt = blockIdx.x, p = blockIdx.y, b = blockIdx.z;
    int n0 = nt * 64;
    __shared__ float xs[CC][64];
    __shared__ float Wt[CC][CC];
    __shared__ float bias[CC];
    int tid = threadIdx.x;
    const float* s1 = x1 + (size_t)b*CC*NN + n0;
    const float* s2 = x2 + (size_t)b*CC*NN + n0;
    for (int idx = tid; idx < CC*64; idx += 256) {
        int ci = idx >> 6, n = idx & 63;
        float v;
        if (p < 2)       v = s1[(size_t)ci*NN + n];
        else if (p < 4)  v = s2[(size_t)ci*NN + n];
        else             v = s1[(size_t)ci*NN + n] + s2[(size_t)ci*NN + n];
        xs[ci][n] = v;
    }
    for (int idx = tid; idx < CC*CC; idx += 256)
        (&Wt[0][0])[idx] = (&g_W[p][b][0][0])[idx];
    if (tid < CC) bias[tid] = g_bias[p][b][tid];
    __syncthreads();

    int cg = tid >> 4;
    int ng = tid & 15;
    float acc[4][4];
    #pragma unroll
    for (int i=0;i<4;i++){ float bv_ = bias[4*cg+i];
        #pragma unroll
        for (int j=0;j<4;j++) acc[i][j]=bv_; }
    for (int ci=0; ci<CC; ci++) {
        float4 w4 = *(const float4*)&Wt[ci][4*cg];
        float4 x4 = *(const float4*)&xs[ci][4*ng];
        float wa[4]={w4.x,w4.y,w4.z,w4.w};
        float xa[4]={x4.x,x4.y,x4.z,x4.w};
        #pragma unroll
        for (int i=0;i<4;i++)
            #pragma unroll
            for (int j=0;j<4;j++) acc[i][j] += wa[i]*xa[j];
    }
    if (p < 4) {
        // [n][c] layout; scale folded into q tensors (p=0,2)
        float fs = (p==0||p==2)? FSCALE : 1.0f;
        #pragma unroll
        for (int j=0;j<4;j++) {
            int n = n0 + 4*ng + j;
            float v0=acc[0][j]*fs, v1=acc[1][j]*fs, v2=acc[2][j]*fs, v3=acc[3][j]*fs;
            uint32_t h01 = packbf(v0, v1), h23 = packbf(v2, v3);
            uint32_t l01 = packbf(v0 - lo2f(h01), v1 - hi2f(h01));
            uint32_t l23 = packbf(v2 - lo2f(h23), v3 - hi2f(h23));
            *(uint2*)&g_ah[p][b][n][4*cg] = make_uint2(h01, h23);
            *(uint2*)&g_al[p][b][n][4*cg] = make_uint2(l01, l23);
        }
    } else {
        // V: [c][n] layout
        #pragma unroll
        for (int i=0;i<4;i++) {
            int c = 4*cg + i;
            float v0=acc[i][0], v1=acc[i][1], v2=acc[i][2], v3=acc[i][3];
            uint32_t h01 = packbf(v0, v1), h23 = packbf(v2, v3);
            uint32_t l01 = packbf(v0 - lo2f(h01), v1 - hi2f(h01));
            uint32_t l23 = packbf(v2 - lo2f(h23), v3 - hi2f(h23));
            *(uint2*)&g_vh[b][c][n0 + 4*ng] = make_uint2(h01, h23);
            *(uint2*)&g_vl[b][c][n0 + 4*ng] = make_uint2(l01, l23);
        }
    }
}

// ============== kernel 4: mma.sync flash attention ==============
// block = (64-query tile, b, branch), 128 threads / 4 warps; warp w owns q rows
// [16w,16w+16). Per kt (64 keys): S = 3-term bf16 split MMA; exp2 softmax in
// registers (FMA pipe); P stays in register fragments; O += 3-term P@V^T.
__global__ void __launch_bounds__(128, 3) k_attn() {
    __shared__ __align__(128) char smem[32768];   // KH|KL|VH|VL 8KB each
    const int OKH = 0, OKL = 8192, OVH = 16384, OVL = 24576;
    uint32_t sb = smem_u32(smem);
    int tid = threadIdx.x, l = tid & 31, w = tid >> 5;
    int qt = blockIdx.x;
    int bbi = blockIdx.y; int b = bbi >> 1, br = bbi & 1;
    int qp = br ? 2 : 0, kp = br ? 3 : 1;

    // ---- load Q tile (hi/lo) into K area, then ldmatrix to registers ----
    {
        const __nv_bfloat16* QH = &g_ah[qp][b][qt*64][0];
        const __nv_bfloat16* QL = &g_al[qp][b][qt*64][0];
        for (int u = tid; u < 512; u += 128) {
            int r = u >> 3, q = u & 7;
            uint32_t off = SWZ(r*128 + q*16);
            *(uint4*)(smem + OKH + off) = ((const uint4*)(QH + r*64))[q];
            *(uint4*)(smem + OKL + off) = ((const uint4*)(QL + r*64))[q];
        }
    }
    __syncthreads();
    uint32_t qh[4][4], ql[4][4];
    {
        int arow = 16*w + ((l>>3)&1)*8 + (l&7);
        int acolh = ((l>>4)&1)*16;
        #pragma unroll
        for (int ks = 0; ks < 4; ks++) {
            uint32_t off = SWZ(arow*128 + ks*32 + acolh);
            ldmx4(qh[ks], sb + OKH + off);
            ldmx4(ql[ks], sb + OKL + off);
        }
    }

    float o[8][4];
    #pragma unroll
    for (int u=0;u<8;u++) { o[u][0]=0.f; o[u][1]=0.f; o[u][2]=0.f; o[u][3]=0.f; }
    float ls0 = 0.f, ls1 = 0.f;

    int brow = ((l>>4)&1)*8 + (l&7);
    int bcolh = ((l>>3)&1)*16;

    for (int kt = 0; kt < 64; kt++) {
        __syncthreads();   // everyone done with previous tiles (and Q on kt=0)
        {   // load K (hi/lo, [j][c]) and V (hi/lo, [c][j]) tiles
            const __nv_bfloat16* KH = &g_ah[kp][b][kt*64][0];
            const __nv_bfloat16* KL = &g_al[kp][b][kt*64][0];
            const __nv_bfloat16* VH = &g_vh[b][0][kt*64];
            const __nv_bfloat16* VL = &g_vl[b][0][kt*64];
            for (int u = tid; u < 512; u += 128) {
                int r = u >> 3, q = u & 7;
                uint32_t off = SWZ(r*128 + q*16);
                *(uint4*)(smem + OKH + off) = ((const uint4*)(KH + r*64))[q];
                *(uint4*)(smem + OKL + off) = ((const uint4*)(KL + r*64))[q];
                *(uint4*)(smem + OVH + off) = *(const uint4*)(VH + (size_t)r*NN + q*8);
                *(uint4*)(smem + OVL + off) = *(const uint4*)(VL + (size_t)r*NN + q*8);
            }
        }
        __syncthreads();
        // ---- S = Qh*Kh + Qh*Kl + Ql*Kh  (8 n-tiles x 4 k-steps) ----
        float s[8][4];
        #pragma unroll
        for (int u=0;u<8;u++) { s[u][0]=0.f; s[u][1]=0.f; s[u][2]=0.f; s[u][3]=0.f; }
        #pragma unroll
        for (int ks = 0; ks < 4; ks++) {
            #pragma unroll
            for (int up = 0; up < 4; up++) {
                uint32_t off = SWZ((16*up + brow)*128 + ks*32 + bcolh);
                uint32_t kh[4], kl[4];
                ldmx4(kh, sb + OKH + off);
                ldmx4(kl, sb + OKL + off);
                mma16816(s[2*up],   qh[ks], kh[0], kh[1]);
                mma16816(s[2*up],   qh[ks], kl[0], kl[1]);
                mma16816(s[2*up],   ql[ks], kh[0], kh[1]);
                mma16816(s[2*up+1], qh[ks], kh[2], kh[3]);
                mma16816(s[2*up+1], qh[ks], kl[2], kl[3]);
                mma16816(s[2*up+1], ql[ks], kh[2], kh[3]);
            }
        }
        // ---- softmax in registers (exp2 domain, no rescale) ----
        uint32_t ph[8][2], pl[8][2];
        #pragma unroll
        for (int u = 0; u < 8; u++) {
            float p0 = fexp2(s[u][0]), p1 = fexp2(s[u][1]);
            float p2 = fexp2(s[u][2]), p3 = fexp2(s[u][3]);
            ls0 += p0 + p1; ls1 += p2 + p3;
            uint32_t hA = packbf(p0, p1), hB = packbf(p2, p3);
            ph[u][0] = hA; ph[u][1] = hB;
            pl[u][0] = packbf(p0 - lo2f(hA), p1 - hi2f(hA));
            pl[u][1] = packbf(p2 - lo2f(hB), p3 - hi2f(hB));
        }
        // ---- O += Ph*Vh + Pl*Vh + Ph*Vl  (8 c-tiles x 4 j-steps) ----
        #pragma unroll
        for (int t = 0; t < 4; t++) {
            uint32_t ah[4] = { ph[2*t][0], ph[2*t][1], ph[2*t+1][0], ph[2*t+1][1] };
            uint32_t al[4] = { pl[2*t][0], pl[2*t][1], pl[2*t+1][0], pl[2*t+1][1] };
            #pragma unroll
            for (int up = 0; up < 4; up++) {
                uint32_t off = SWZ((16*up + brow)*128 + t*32 + bcolh);
                uint32_t vh[4], vl[4];
                ldmx4(vh, sb + OVH + off);
                ldmx4(vl, sb + OVL + off);
                mma16816(o[2*up],   ah, vh[0], vh[1]);
                mma16816(o[2*up],   al, vh[0], vh[1]);
                mma16816(o[2*up],   ah, vl[0], vl[1]);
                mma16816(o[2*up+1], ah, vh[2], vh[3]);
                mma16816(o[2*up+1], al, vh[2], vh[3]);
                mma16816(o[2*up+1], ah, vl[2], vl[3]);
            }
        }
    }
    // ---- row sums across the quad, normalize ----
    ls0 += __shfl_xor_sync(0xffffffffu, ls0, 1);
    ls0 += __shfl_xor_sync(0xffffffffu, ls0, 2);
    ls1 += __shfl_xor_sync(0xffffffffu, ls1, 1);
    ls1 += __shfl_xor_sync(0xffffffffu, ls1, 2);
    float ri0 = 1.0f / ls0, ri1 = 1.0f / ls1;
    #pragma unroll
    for (int u=0;u<8;u++) { o[u][0]*=ri0; o[u][1]*=ri0; o[u][2]*=ri1; o[u][3]*=ri1; }
    // ---- transpose 16x64 -> [c][n] via smem, write g_h ----
    __syncthreads();
    float* W = (float*)smem + w * 1088;          // 64 rows x stride 17
    #pragma unroll
    for (int u = 0; u < 8; u++) {
        int c0 = 8*u + 2*(l&3);
        int r  = l >> 2;
        W[c0*17 + r]       = o[u][0];
        W[(c0+1)*17 + r]   = o[u][1];
        W[c0*17 + r + 8]   = o[u][2];
        W[(c0+1)*17 + r+8] = o[u][3];
    }
    __syncwarp();
    float* H = &g_h[br][b][0][0];
    int n0 = qt*64 + w*16;
    #pragma unroll
    for (int rep = 0; rep < 2; rep++) {
        int cc = 2*l + rep;
        #pragma unroll
        for (int k4 = 0; k4 < 4; k4++) {
            float4 v = make_float4(W[cc*17+4*k4], W[cc*17+4*k4+1],
                                   W[cc*17+4*k4+2], W[cc*17+4*k4+3]);
            *(float4*)&H[(size_t)cc*NN + n0 + 4*k4] = v;
        }
    }
}

// ================= kernel 5: final combine =================
__global__ void k_final(const float* __restrict__ x1, const float* __restrict__ x2,
                        float* __restrict__ out) {
    int idx4 = blockIdx.x*256 + threadIdx.x;
    if (idx4 >= BB*CC*NN/4) return;
    int idx = idx4 * 4;
    int bc = idx >> 12;
    int b = bc >> 6, c = bc & 63;
    float se = g_se[b][c];
    float4 a1 = *(const float4*)&x1[idx];
    float4 a2 = *(const float4*)&x2[idx];
    float4 h1 = *(const float4*)(&g_h[0][0][0][0] + idx);
    float4 h2 = *(const float4*)(&g_h[1][0][0][0] + idx);
    float xs[4] = {a1.x+a2.x, a1.y+a2.y, a1.z+a2.z, a1.w+a2.w};
    float h1a[4]={h1.x,h1.y,h1.z,h1.w};
    float h2a[4]={h2.x,h2.y,h2.z,h2.w};
    float oa[4];
    #pragma unroll
    for (int k=0;k<4;k++) {
        float ww = 1.f/(1.f+fexp(-xs[k]*se));
        oa[k] = 2.f*h1a[k]*ww + 2.f*h2a[k]*(1.f-ww);
    }
    *(float4*)&out[idx] = make_float4(oa[0],oa[1],oa[2],oa[3]);
}

// ================= launcher =================
extern "C" void kernel_launch(void* const* d_in, const int* in_sizes, int n_in,
                              void* d_out, int out_size) {
    const float* x1    = (const float*)d_in[0];
    const float* x2    = (const float*)d_in[1];
    const float* se_w1 = (const float*)d_in[2];
    const float* se_w2 = (const float*)d_in[3];
    const float* gam   = (const float*)d_in[4];
    const float* bet   = (const float*)d_in[5];
    const float* wq    = (const float*)d_in[6];
    const float* bq    = (const float*)d_in[7];
    const float* wk    = (const float*)d_in[8];
    const float* bk    = (const float*)d_in[9];
    const float* wv    = (const float*)d_in[10];
    const float* bv    = (const float*)d_in[11];
    float* out = (float*)d_out;

    k_stats<<<BB*CC, 256>>>(x1, x2);
    k_prep<<<BB, CC>>>(se_w1, se_w2, gam, bet, wq, bq, wk, bk, wv, bv);
    k_proj<<<dim3(64, 5, BB), 256>>>(x1, x2);
    k_attn<<<dim3(64, 8), 128>>>();
    k_final<<<(BB*CC*NN/4 + 255)/256, 256>>>(x1, x2, out);
}

// round 7
// speedup vs baseline: 3.9608x; 1.3718x over previous
#include <cuda_runtime.h>
#include <cuda_fp16.h>
#include <math.h>
#include <stdint.h>

#define BB 4
#define CC 64
#define NN 4096
#define RR 4
#define EPSF 1e-6f
#define FSCALE 0.18033688011112042f   // 0.125 * log2(e), folded into Q

// ---------------- helpers ----------------
__device__ __forceinline__ uint32_t smem_u32(const void* p) {
    uint32_t a;
    asm("{ .reg .u64 t; cvta.to.shared.u64 t, %1; cvt.u32.u64 %0, t; }" : "=r"(a) : "l"(p));
    return a;
}
#define SWZ(off) ((off) ^ (((off) >> 3) & 0x70))   // SW128-style row swizzle

__device__ __forceinline__ void ldmx4(uint32_t* r, uint32_t addr) {
    asm volatile("ldmatrix.sync.aligned.m8n8.x4.shared.b16 {%0,%1,%2,%3}, [%4];"
        : "=r"(r[0]), "=r"(r[1]), "=r"(r[2]), "=r"(r[3]) : "r"(addr));
}
__device__ __forceinline__ void mma16816(float* d, const uint32_t* a,
                                         uint32_t b0, uint32_t b1) {
    asm volatile("mma.sync.aligned.m16n8k16.row.col.f32.f16.f16.f32 "
        "{%0,%1,%2,%3}, {%4,%5,%6,%7}, {%8,%9}, {%0,%1,%2,%3};"
        : "+f"(d[0]), "+f"(d[1]), "+f"(d[2]), "+f"(d[3])
        : "r"(a[0]), "r"(a[1]), "r"(a[2]), "r"(a[3]), "r"(b0), "r"(b1));
}
__device__ __forceinline__ uint32_t packh2(float lo, float hi) {  // lower=lo, upper=hi
    uint32_t r; asm("cvt.rn.f16x2.f32 %0, %1, %2;" : "=r"(r) : "f"(hi), "f"(lo)); return r;
}
#define CP_A16(dst, src) \
    asm volatile("cp.async.cg.shared.global [%0], [%1], 16;" :: "r"(dst), "l"(src) : "memory")
#define CP_COMMIT() asm volatile("cp.async.commit_group;" ::: "memory")
#define CP_WAIT(n)  asm volatile("cp.async.wait_group %0;" :: "n"(n) : "memory")

// FMA-pipe exp2 (keeps exps OFF the MUFU pipe; rel err ~2e-6)
__device__ __forceinline__ float fexp2(float x) {
    const float MAGIC = 12582912.0f;          // 1.5 * 2^23
    x = fmaxf(x, -80.0f);
    float nf = x + MAGIC;
    float f  = x - (nf - MAGIC);              // f in [-0.5, 0.5]
    float p = 1.3333558146e-3f;
    p = fmaf(p, f, 9.6181298421e-3f);
    p = fmaf(p, f, 5.5504108665e-2f);
    p = fmaf(p, f, 2.4022650696e-1f);
    p = fmaf(p, f, 6.9314718056e-1f);
    p = fmaf(p, f, 1.0f);
    int r = __float_as_int(p) + (__float_as_int(nf) << 23);
    return __int_as_float(r);
}
__device__ __forceinline__ float fexp(float x) {   // e^x for sigmoids
    return fexp2(x * 1.4426950408889634f);
}

// ---------------- scratch (device globals) ----------------
__device__ float g_stat[BB][CC][6];
__device__ float g_se[BB][CC];
__device__ float g_W[5][BB][CC][CC];
__device__ float g_bias[5][BB][CC];
__device__ __half g_qh[2][BB][NN][CC];   // Q hi, per branch, [n][c], scaled by FSCALE
__device__ __half g_ql[2][BB][NN][CC];   // Q lo
__device__ __half g_k [2][BB][NN][CC];   // K single fp16, [n][c]
__device__ __half g_v [BB][CC][NN];      // V single fp16, [c][n]
__device__ float g_h[2][BB][CC][NN];     // attention outputs

// ================= kernel 1: per-(b,c) sums over HW =================
__global__ void k_stats(const float* __restrict__ x1, const float* __restrict__ x2) {
    int bc = blockIdx.x;
    const float* p1 = x1 + (size_t)bc * NN;
    const float* p2 = x2 + (size_t)bc * NN;
    float s1=0.f,q1=0.f,s2=0.f,q2=0.f,sx=0.f,qx=0.f;
    for (int i = threadIdx.x; i < NN; i += 256) {
        float a = p1[i], b_ = p2[i], s = a + b_;
        s1 += a; q1 += a*a; s2 += b_; q2 += b_*b_; sx += s; qx += s*s;
    }
    __shared__ float red[6][256];
    red[0][threadIdx.x]=s1; red[1][threadIdx.x]=q1; red[2][threadIdx.x]=s2;
    red[3][threadIdx.x]=q2; red[4][threadIdx.x]=sx; red[5][threadIdx.x]=qx;
    __syncthreads();
    for (int off=128; off>=1; off>>=1) {
        if (threadIdx.x < (unsigned)off) {
            #pragma unroll
            for (int k=0;k<6;k++) red[k][threadIdx.x] += red[k][threadIdx.x+off];
        }
        __syncthreads();
    }
    if (threadIdx.x < 6) g_stat[bc/CC][bc%CC][threadIdx.x] = red[threadIdx.x][0];
}

// ============ kernel 2: SE MLP + GroupNorm fold into weights ============
__global__ void k_prep(const float* __restrict__ se_w1, const float* __restrict__ se_w2,
                       const float* __restrict__ gamma, const float* __restrict__ beta,
                       const float* __restrict__ wq, const float* __restrict__ bq,
                       const float* __restrict__ wk, const float* __restrict__ bk,
                       const float* __restrict__ wv, const float* __restrict__ bv) {
    int b = blockIdx.x;
    int c = threadIdx.x;
    __shared__ float sy[CC], sh[RR], sA[3][CC], sBc[3][CC];
    float st[6], stp[6];
    #pragma unroll
    for (int k=0;k<6;k++) st[k] = g_stat[b][c][k];
    int cp = c ^ 1;
    #pragma unroll
    for (int k=0;k<6;k++) stp[k] = g_stat[b][cp][k];

    sy[c] = st[4] * (1.0f/NN);
    __syncthreads();
    if (c < RR) {
        float h = 0.f;
        for (int ci=0; ci<CC; ci++) h += se_w1[c*CC+ci]*sy[ci];
        sh[c] = fmaxf(h, 0.f);
    }
    __syncthreads();
    {
        float z = 0.f;
        #pragma unroll
        for (int r=0;r<RR;r++) z += se_w2[c*RR+r]*sh[r];
        g_se[b][c] = 1.f/(1.f+fexp(-z));
    }
    const float inv = 1.0f/(2.0f*NN);
    float ga = gamma[c], be = beta[c];
    #pragma unroll
    for (int t=0;t<3;t++) {
        float mean = (st[2*t]+stp[2*t])*inv;
        float var  = (st[2*t+1]+stp[2*t+1])*inv - mean*mean;
        float rs = rsqrtf(var + EPSF);
        float A = rs*ga;
        sA[t][c] = A;
        sBc[t][c] = be - mean*A;
    }
    __syncthreads();
    for (int p=0;p<5;p++) {
        const float* w  = (p==0||p==2)? wq : (p==1||p==3)? wk : wv;
        const float* bb = (p==0||p==2)? bq : (p==1||p==3)? bk : bv;
        int t = (p<2)?0 : (p<4)?1 : 2;
        float acc = bb[c];
        for (int ci=0; ci<CC; ci++) {
            float wvl = w[c*CC+ci];
            acc += wvl * sBc[t][ci];
            g_W[p][b][ci][c] = wvl * sA[t][ci];
        }
        g_bias[p][b][c] = acc;
    }
}

// ====== kernel 3: projections -> fp16 operand tensors ======
__global__ void __launch_bounds__(256) k_proj(const float* __restrict__ x1,
                                              const float* __restrict__ x2) {
    int nt = blockIdx.x, p = blockIdx.y, b = blockIdx.z;
    int n0 = nt * 64;
    __shared__ float xs[CC][64];
    __shared__ float Wt[CC][CC];
    __shared__ float bias[CC];
    int tid = threadIdx.x;
    const float* s1 = x1 + (size_t)b*CC*NN + n0;
    const float* s2 = x2 + (size_t)b*CC*NN + n0;
    for (int idx = tid; idx < CC*64; idx += 256) {
        int ci = idx >> 6, n = idx & 63;
        float v;
        if (p < 2)       v = s1[(size_t)ci*NN + n];
        else if (p < 4)  v = s2[(size_t)ci*NN + n];
        else             v = s1[(size_t)ci*NN + n] + s2[(size_t)ci*NN + n];
        xs[ci][n] = v;
    }
    for (int idx = tid; idx < CC*CC; idx += 256)
        (&Wt[0][0])[idx] = (&g_W[p][b][0][0])[idx];
    if (tid < CC) bias[tid] = g_bias[p][b][tid];
    __syncthreads();

    int cg = tid >> 4;
    int ng = tid & 15;
    float acc[4][4];
    #pragma unroll
    for (int i=0;i<4;i++){ float bv_ = bias[4*cg+i];
        #pragma unroll
        for (int j=0;j<4;j++) acc[i][j]=bv_; }
    for (int ci=0; ci<CC; ci++) {
        float4 w4 = *(const float4*)&Wt[ci][4*cg];
        float4 x4 = *(const float4*)&xs[ci][4*ng];
        float wa[4]={w4.x,w4.y,w4.z,w4.w};
        float xa[4]={x4.x,x4.y,x4.z,x4.w};
        #pragma unroll
        for (int i=0;i<4;i++)
            #pragma unroll
            for (int j=0;j<4;j++) acc[i][j] += wa[i]*xa[j];
    }
    if (p == 0 || p == 2) {
        // Q: 2-term fp16 split, [n][c], scale folded in
        int br = p >> 1;
        #pragma unroll
        for (int j=0;j<4;j++) {
            int n = n0 + 4*ng + j;
            float v0=acc[0][j]*FSCALE, v1=acc[1][j]*FSCALE;
            float v2=acc[2][j]*FSCALE, v3=acc[3][j]*FSCALE;
            uint32_t h01 = packh2(v0, v1), h23 = packh2(v2, v3);
            float r0 = __half2float(__ushort_as_half((unsigned short)(h01 & 0xffff)));
            float r1 = __half2float(__ushort_as_half((unsigned short)(h01 >> 16)));
            float r2 = __half2float(__ushort_as_half((unsigned short)(h23 & 0xffff)));
            float r3 = __half2float(__ushort_as_half((unsigned short)(h23 >> 16)));
            uint32_t l01 = packh2(v0 - r0, v1 - r1), l23 = packh2(v2 - r2, v3 - r3);
            *(uint2*)&g_qh[br][b][n][4*cg] = make_uint2(h01, h23);
            *(uint2*)&g_ql[br][b][n][4*cg] = make_uint2(l01, l23);
        }
    } else if (p == 1 || p == 3) {
        // K: single fp16, [n][c]
        int br = p >> 1;
        #pragma unroll
        for (int j=0;j<4;j++) {
            int n = n0 + 4*ng + j;
            uint32_t h01 = packh2(acc[0][j], acc[1][j]);
            uint32_t h23 = packh2(acc[2][j], acc[3][j]);
            *(uint2*)&g_k[br][b][n][4*cg] = make_uint2(h01, h23);
        }
    } else {
        // V: single fp16, [c][n]
        #pragma unroll
        for (int i=0;i<4;i++) {
            int c = 4*cg + i;
            uint32_t h01 = packh2(acc[i][0], acc[i][1]);
            uint32_t h23 = packh2(acc[i][2], acc[i][3]);
            *(uint2*)&g_v[b][c][n0 + 4*ng] = make_uint2(h01, h23);
        }
    }
}

// ============== kernel 4: mma.sync flash attention, fp16 2-term ==============
// 128 thr / 4 warps; warp w owns q rows [16w,16w+16). Double-buffered K|V tiles
// (16KB each) streamed by cp.async; S = (Qh+Ql)K, P split hi/lo, O += (Ph+Pl)V.
__global__ void __launch_bounds__(128, 4) k_attn() {
    __shared__ __align__(128) char smem[32768];   // 2 x (K 8KB | V 8KB)
    uint32_t sb = smem_u32(smem);
    int tid = threadIdx.x, l = tid & 31, w = tid >> 5;
    int qt = blockIdx.x;
    int bbi = blockIdx.y; int b = bbi >> 1, br = bbi & 1;

    const __half* QH = &g_qh[br][b][qt*64][0];
    const __half* QL = &g_ql[br][b][qt*64][0];
    const __half* K  = &g_k[br][b][0][0];
    const __half* V  = &g_v[b][0][0];

    // ---- Q tile into buf0 (plain), ldmatrix to regs ----
    for (int u = tid; u < 512; u += 128) {
        int r = u >> 3, q = u & 7;
        uint32_t off = SWZ(r*128 + q*16);
        *(uint4*)(smem + off)        = ((const uint4*)(QH + r*64))[q];
        *(uint4*)(smem + 8192 + off) = ((const uint4*)(QL + r*64))[q];
    }
    __syncthreads();
    uint32_t qh[4][4], ql[4][4];
    {
        int arow = 16*w + ((l>>3)&1)*8 + (l&7);
        int acolh = ((l>>4)&1)*16;
        #pragma unroll
        for (int ks = 0; ks < 4; ks++) {
            uint32_t off = SWZ(arow*128 + ks*32 + acolh);
            ldmx4(qh[ks], sb + off);
            ldmx4(ql[ks], sb + 8192 + off);
        }
    }
    __syncthreads();

    // ---- preload tiles 0 and 1 ----
    #pragma unroll
    for (int pre = 0; pre < 2; pre++) {
        uint32_t base = sb + pre*16384;
        const __half* kg = K + (size_t)pre*64*CC;
        const __half* vg = V + pre*64;
        for (int u = tid; u < 512; u += 128) {
            int r = u >> 3, q = u & 7;
            uint32_t off = SWZ(r*128 + q*16);
            CP_A16(base + off,        kg + r*64 + q*8);
            CP_A16(base + 8192 + off, vg + (size_t)r*NN + q*8);
        }
        CP_COMMIT();
    }

    float o[8][4];
    #pragma unroll
    for (int u=0;u<8;u++) { o[u][0]=0.f; o[u][1]=0.f; o[u][2]=0.f; o[u][3]=0.f; }
    float ls0 = 0.f, ls1 = 0.f;

    int brow = ((l>>4)&1)*8 + (l&7);
    int bcolh = ((l>>3)&1)*16;

    for (int kt = 0; kt < 64; kt++) {
        if (kt == 63) { CP_WAIT(0); } else { CP_WAIT(1); }
        __syncthreads();
        uint32_t base = sb + (kt&1)*16384;
        // ---- S = Qh*K + Ql*K  (4 ks x 4 up x 4 MMA) ----
        float s[8][4];
        #pragma unroll
        for (int u=0;u<8;u++) { s[u][0]=0.f; s[u][1]=0.f; s[u][2]=0.f; s[u][3]=0.f; }
        #pragma unroll
        for (int ks = 0; ks < 4; ks++) {
            #pragma unroll
            for (int up = 0; up < 4; up++) {
                uint32_t kh[4];
                ldmx4(kh, base + SWZ((16*up + brow)*128 + ks*32 + bcolh));
                mma16816(s[2*up],   qh[ks], kh[0], kh[1]);
                mma16816(s[2*up+1], qh[ks], kh[2], kh[3]);
                mma16816(s[2*up],   ql[ks], kh[0], kh[1]);
                mma16816(s[2*up+1], ql[ks], kh[2], kh[3]);
            }
        }
        // ---- softmax (exp2 domain) + fp16 hi/lo split of P ----
        uint32_t ph[8][2], pl[8][2];
        #pragma unroll
        for (int u = 0; u < 8; u++) {
            float p0 = fexp2(s[u][0]), p1 = fexp2(s[u][1]);
            float p2 = fexp2(s[u][2]), p3 = fexp2(s[u][3]);
            ls0 += p0 + p1; ls1 += p2 + p3;
            uint32_t hA = packh2(p0, p1), hB = packh2(p2, p3);
            float r0 = __half2float(__ushort_as_half((unsigned short)(hA & 0xffff)));
            float r1 = __half2float(__ushort_as_half((unsigned short)(hA >> 16)));
            float r2 = __half2float(__ushort_as_half((unsigned short)(hB & 0xffff)));
            float r3 = __half2float(__ushort_as_half((unsigned short)(hB >> 16)));
            ph[u][0] = hA; ph[u][1] = hB;
            pl[u][0] = packh2(p0 - r0, p1 - r1);
            pl[u][1] = packh2(p2 - r2, p3 - r3);
        }
        // ---- O += Ph*V + Pl*V  (4 t x 4 up x 4 MMA) ----
        #pragma unroll
        for (int t = 0; t < 4; t++) {
            uint32_t ah[4] = { ph[2*t][0], ph[2*t][1], ph[2*t+1][0], ph[2*t+1][1] };
            uint32_t al[4] = { pl[2*t][0], pl[2*t][1], pl[2*t+1][0], pl[2*t+1][1] };
            #pragma unroll
            for (int up = 0; up < 4; up++) {
                uint32_t vh[4];
                ldmx4(vh, base + 8192 + SWZ((16*up + brow)*128 + t*32 + bcolh));
                mma16816(o[2*up],   ah, vh[0], vh[1]);
                mma16816(o[2*up+1], ah, vh[2], vh[3]);
                mma16816(o[2*up],   al, vh[0], vh[1]);
                mma16816(o[2*up+1], al, vh[2], vh[3]);
            }
        }
        __syncthreads();     // all warps done reading buf[kt&1]
        if (kt < 62) {       // stream tile kt+2 into the freed buffer
            int nt2 = kt + 2;
            const __half* kg = K + (size_t)nt2*64*CC;
            const __half* vg = V + nt2*64;
            for (int u = tid; u < 512; u += 128) {
                int r = u >> 3, q = u & 7;
                uint32_t off = SWZ(r*128 + q*16);
                CP_A16(base + off,        kg + r*64 + q*8);
                CP_A16(base + 8192 + off, vg + (size_t)r*NN + q*8);
            }
            CP_COMMIT();
        }
    }
    // ---- row sums across the quad, normalize ----
    ls0 += __shfl_xor_sync(0xffffffffu, ls0, 1);
    ls0 += __shfl_xor_sync(0xffffffffu, ls0, 2);
    ls1 += __shfl_xor_sync(0xffffffffu, ls1, 1);
    ls1 += __shfl_xor_sync(0xffffffffu, ls1, 2);
    float ri0 = 1.0f / ls0, ri1 = 1.0f / ls1;
    #pragma unroll
    for (int u=0;u<8;u++) { o[u][0]*=ri0; o[u][1]*=ri0; o[u][2]*=ri1; o[u][3]*=ri1; }
    // ---- transpose 16x64 -> [c][n] via smem, write g_h ----
    __syncthreads();
    float* W = (float*)smem + w * 1088;          // 64 rows x stride 17
    #pragma unroll
    for (int u = 0; u < 8; u++) {
        int c0 = 8*u + 2*(l&3);
        int r  = l >> 2;
        W[c0*17 + r]       = o[u][0];
        W[(c0+1)*17 + r]   = o[u][1];
        W[c0*17 + r + 8]   = o[u][2];
        W[(c0+1)*17 + r+8] = o[u][3];
    }
    __syncwarp();
    float* H = &g_h[br][b][0][0];
    int n0 = qt*64 + w*16;
    #pragma unroll
    for (int rep = 0; rep < 2; rep++) {
        int cc = 2*l + rep;
        #pragma unroll
        for (int k4 = 0; k4 < 4; k4++) {
            float4 v = make_float4(W[cc*17+4*k4], W[cc*17+4*k4+1],
                                   W[cc*17+4*k4+2], W[cc*17+4*k4+3]);
            *(float4*)&H[(size_t)cc*NN + n0 + 4*k4] = v;
        }
    }
}

// ================= kernel 5: final combine =================
__global__ void k_final(const float* __restrict__ x1, const float* __restrict__ x2,
                        float* __restrict__ out) {
    int idx4 = blockIdx.x*256 + threadIdx.x;
    if (idx4 >= BB*CC*NN/4) return;
    int idx = idx4 * 4;
    int bc = idx >> 12;
    int b = bc >> 6, c = bc & 63;
    float se = g_se[b][c];
    float4 a1 = *(const float4*)&x1[idx];
    float4 a2 = *(const float4*)&x2[idx];
    float4 h1 = *(const float4*)(&g_h[0][0][0][0] + idx);
    float4 h2 = *(const float4*)(&g_h[1][0][0][0] + idx);
    float xs[4] = {a1.x+a2.x, a1.y+a2.y, a1.z+a2.z, a1.w+a2.w};
    float h1a[4]={h1.x,h1.y,h1.z,h1.w};
    float h2a[4]={h2.x,h2.y,h2.z,h2.w};
    float oa[4];
    #pragma unroll
    for (int k=0;k<4;k++) {
        float ww = 1.f/(1.f+fexp(-xs[k]*se));
        oa[k] = 2.f*h1a[k]*ww + 2.f*h2a[k]*(1.f-ww);
    }
    *(float4*)&out[idx] = make_float4(oa[0],oa[1],oa[2],oa[3]);
}

// ================= launcher =================
extern "C" void kernel_launch(void* const* d_in, const int* in_sizes, int n_in,
                              void* d_out, int out_size) {
    const float* x1    = (const float*)d_in[0];
    const float* x2    = (const float*)d_in[1];
    const float* se_w1 = (const float*)d_in[2];
    const float* se_w2 = (const float*)d_in[3];
    const float* gam   = (const float*)d_in[4];
    const float* bet   = (const float*)d_in[5];
    const float* wq    = (const float*)d_in[6];
    const float* bq    = (const float*)d_in[7];
    const float* wk    = (const float*)d_in[8];
    const float* bk    = (const float*)d_in[9];
    const float* wv    = (const float*)d_in[10];
    const float* bv    = (const float*)d_in[11];
    float* out = (float*)d_out;

    k_stats<<<BB*CC, 256>>>(x1, x2);
    k_prep<<<BB, CC>>>(se_w1, se_w2, gam, bet, wq, bq, wk, bk, wv, bv);
    k_proj<<<dim3(64, 5, BB), 256>>>(x1, x2);
    k_attn<<<dim3(64, 8), 128>>>();
    k_final<<<(BB*CC*NN/4 + 255)/256, 256>>>(x1, x2, out);
}